// round 15
// baseline (speedup 1.0000x reference)
#include <cuda_runtime.h>
#include <cuda_fp16.h>
#include <math.h>
#include <stdint.h>

#define T_STEPS 256
#define BATCH   256
#define OBSD    128
#define HIDD    256
#define HS      512
#define G4      2048
#define ACTD    16
#define TBROWS  (T_STEPS * BATCH)
#define NCTA    128
typedef __half HF;

// ---------------- scratch (static device arrays; no cudaMalloc) ----------------
__device__ __align__(16) HF    g_fH[(size_t)TBROWS * HIDD];   // feats fp16
__device__ __align__(16) HF    g_hH[(size_t)TBROWS * HS];     // h fp16
__device__ __align__(16) HF    g_Wh[(size_t)G4 * HS];         // [n][k] permuted+transposed fp16
__device__ __align__(16) HF    g_Wi[(size_t)G4 * HIDD];
__device__ __align__(16) float g_bP[G4];
__device__ __align__(128) unsigned g_cntA[128];               // per-mb barrier counters (mb*32)

__device__ __forceinline__ float sigmf(float x) { return 1.0f / (1.0f + expf(-x)); }
__device__ __forceinline__ float geluf(float v) {
    float u = 0.7978845608028654f * (v + 0.044715f * v * v * v);
    return 0.5f * v * (1.0f + tanhf(u));
}
__device__ __forceinline__ uint32_t smem_u32(const void* p) {
    uint32_t a;
    asm("{ .reg .u64 t; cvta.to.shared.u64 t, %1; cvt.u32.u64 %0, t; }" : "=r"(a) : "l"(p));
    return a;
}
__device__ __forceinline__ void ldmx4(uint32_t addr, uint32_t* r) {
    asm volatile("ldmatrix.sync.aligned.m8n8.x4.shared.b16 {%0,%1,%2,%3}, [%4];"
        : "=r"(r[0]), "=r"(r[1]), "=r"(r[2]), "=r"(r[3]) : "r"(addr));
}
__device__ __forceinline__ void mma16816(float* d, const uint32_t* a, const uint32_t* b) {
    asm volatile("mma.sync.aligned.m16n8k16.row.col.f32.f16.f16.f32 "
        "{%0,%1,%2,%3}, {%4,%5,%6,%7}, {%8,%9}, {%0,%1,%2,%3};"
        : "+f"(d[0]), "+f"(d[1]), "+f"(d[2]), "+f"(d[3])
        : "r"(a[0]), "r"(a[1]), "r"(a[2]), "r"(a[3]), "r"(b[0]), "r"(b[1]));
}
#define CP_COMMIT() asm volatile("cp.async.commit_group;" ::: "memory")
#define CP_WAIT0()  asm volatile("cp.async.wait_group 0;" ::: "memory")
__device__ __forceinline__ void flag_arrive(unsigned* f) {
    asm volatile("red.release.gpu.global.add.u32 [%0], %1;" :: "l"(f), "r"(1u) : "memory");
}
__device__ __forceinline__ void flag_spin(const unsigned* f, unsigned target) {
    unsigned v;
    do {
        asm volatile("ld.acquire.gpu.global.u32 %0, [%1];" : "=r"(v) : "l"(f) : "memory");
    } while (v < target);
}

// A stage stride: 136 halves (272B, ≡16 mod 128 -> conflict-free ldmatrix)
#define AST 136
#define CHUNK_BYTES 17408          // 64 x 136 halves
// ---- scan SMEM map (bytes) ----
#define S_WH   0                   // Wh slice 64x520 halves = 66560
#define S_WI   66560               // Wi slice 64x264 halves = 33792
#define S_HB   100352              // h stage: 4 chunks x 17408 = 69632
#define S_PART 100352              // part[4][64][68] f32 = 69632 -> aliases all h bufs
#define S_FB   169984              // feats stage: 2 sub-chunks of 17408 = 34816
#define S_CS   204800              // cell state 64x16 fp32 = 4096
#define S_BS   208896              // bias slice 64 f32 = 256
#define S_DYN  209152
#define WST_H  520
#define WST_I  264

// cp.async one K=128 chunk (64 rows) of fp16 A into stage buffer (512 thr)
__device__ __forceinline__ void stage_cp(uint32_t dst, const HF* src, int ld, int tid) {
#pragma unroll
    for (int p = 0; p < 2; p++) {
        int j = tid + p * 512;
        int r = j >> 4, cb = j & 15;
        const HF* s = src + (size_t)r * ld + cb * 8;
        uint32_t d = dst + r * 272 + cb * 16;
        asm volatile("cp.async.cg.shared.global [%0], [%1], 16;" :: "r"(d), "l"(s));
    }
}
// stage all 4 h chunks (K=512) in one burst
__device__ __forceinline__ void stage_h_all(uint32_t dst, const HF* src, int tid) {
#pragma unroll
    for (int ch = 0; ch < 4; ch++)
        stage_cp(dst + ch * CHUNK_BYTES, src + ch * 128, HS, tid);
}

// Warp (ng in [0,4), kg in [0,4)): m64 x n16 tile, single fp16 pass,
// 2 ksteps (kg*2, kg*2+1) of a 128-col A chunk against W ksteps wkbase+...
__device__ __forceinline__ void mma_1p(uint32_t aBuf, uint32_t wBuf, int wst,
                                       int kg, int wkbase, int ng, int lane,
                                       float acc[4][2][4]) {
#pragma unroll
    for (int s = 0; s < 2; s++) {
        int lks = kg * 2 + s;
        int wks = wkbase + lks;
        uint32_t bh[4];
        int nrow = ng * 16 + (lane & 7) + ((lane >> 4) << 3);
        int kcol = wks * 16 + ((lane >> 3) & 1) * 8;
        ldmx4(wBuf + (nrow * wst + kcol) * 2, bh);
#pragma unroll
        for (int mt = 0; mt < 4; mt++) {
            uint32_t ah[4];
            int row = mt * 16 + (lane & 15);
            int col = lks * 16 + ((lane >> 4) << 3);
            ldmx4(aBuf + (row * AST + col) * 2, ah);
#pragma unroll
            for (int q = 0; q < 2; q++)
                mma16816(acc[mt][q], ah, &bh[q * 2]);
        }
    }
}

// STS all k-split partials: part[kg][64][68]
__device__ __forceinline__ void sts_part_all(float* part, float acc[4][2][4],
                                             int kg, int ng, int lane) {
#pragma unroll
    for (int mt = 0; mt < 4; mt++)
#pragma unroll
        for (int nt = 0; nt < 2; nt++) {
            int row0 = mt * 16 + (lane >> 2);
            int col = ng * 16 + nt * 8 + (lane & 3) * 2;
            *(float2*)&part[(kg * 64 + row0) * 68 + col] = *(float2*)&acc[mt][nt][0];
            *(float2*)&part[(kg * 64 + row0 + 8) * 68 + col] = *(float2*)&acc[mt][nt][2];
        }
}

// ---------------- prep: permuted+transposed fp16 weights ----------------
__global__ void prep_kernel(const float* __restrict__ Wi, const float* __restrict__ Wh,
                            const float* __restrict__ bl) {
    int stride = gridDim.x * blockDim.x;
    int idx = blockIdx.x * blockDim.x + threadIdx.x;
    for (int i = idx; i < G4 * HS; i += stride) {
        int n = i >> 9, k = i & (HS - 1);
        g_Wh[i] = __float2half(Wh[(size_t)k * G4 + (n & 3) * HS + (n >> 2)]);
    }
    for (int i = idx; i < G4 * HIDD; i += stride) {
        int n = i >> 8, k = i & (HIDD - 1);
        g_Wi[i] = __float2half(Wi[(size_t)k * G4 + (n & 3) * HS + (n >> 2)]);
    }
    for (int i = idx; i < G4; i += stride)
        g_bP[i] = bl[(i & 3) * HS + (i >> 2)];
    if (idx < 128) g_cntA[idx] = 0;
}

// ---------------- encoder: feats = gelu(x@W_enc + b) -> fp16 ----------------
__global__ void __launch_bounds__(256) enc_kernel(const float* __restrict__ A,
                                                  const float* __restrict__ B,
                                                  const float* __restrict__ bias) {
    __shared__ float As[64 * 68];
    __shared__ float Bs[64 * 64];
    int nb = blockIdx.x, mb = blockIdx.y, tid = threadIdx.x;
    int tn = tid & 15, tm = tid >> 4;
    float acc[4][4];
#pragma unroll
    for (int i = 0; i < 4; i++)
#pragma unroll
        for (int j = 0; j < 4; j++) acc[i][j] = 0.f;
    for (int kc = 0; kc < 2; kc++) {
        __syncthreads();
#pragma unroll
        for (int p = 0; p < 4; p++) {
            int idx = p * 256 + tid, r = idx >> 4, c4 = (idx & 15) << 2;
            *(float4*)&As[r * 68 + c4] = *(const float4*)&A[(size_t)(mb * 64 + r) * OBSD + kc * 64 + c4];
            *(float4*)&Bs[r * 64 + c4] = *(const float4*)&B[(size_t)(kc * 64 + r) * HIDD + nb * 64 + c4];
        }
        __syncthreads();
#pragma unroll 8
        for (int kk = 0; kk < 64; kk++) {
            float4 w = *(const float4*)&Bs[kk * 64 + tn * 4];
#pragma unroll
            for (int i = 0; i < 4; i++) {
                float a = As[(tm * 4 + i) * 68 + kk];
                acc[i][0] += a * w.x; acc[i][1] += a * w.y;
                acc[i][2] += a * w.z; acc[i][3] += a * w.w;
            }
        }
    }
    int n0 = nb * 64 + tn * 4;
    float4 bb = *(const float4*)&bias[n0];
#pragma unroll
    for (int i = 0; i < 4; i++) {
        int row = mb * 64 + tm * 4 + i;
        __align__(8) HF hb[4];
        hb[0] = __float2half(geluf(acc[i][0] + bb.x));
        hb[1] = __float2half(geluf(acc[i][1] + bb.y));
        hb[2] = __float2half(geluf(acc[i][2] + bb.z));
        hb[3] = __float2half(geluf(acc[i][3] + bb.w));
        *(int2*)(g_fH + (size_t)row * HIDD + n0) = *(int2*)hb;
    }
}

// ---------------- fused persistent LSTM scan (feats MMA in barrier shadow) ----------------
// 128 CTAs = 4 mb(64 batch) x 32 nb(64 gate cols). 16 warps = 4 ng x 4 kg.
// acc is PRE-LOADED with feats(t)@Wi in the tail of step t-1 (after flag_arrive,
// while other CTAs converge). Step t's critical path: spin -> h burst -> h MMA -> epi.
__global__ void __launch_bounds__(512) scan_mma_kernel() {
    extern __shared__ char sm[];
    uint32_t sb = smem_u32(sm);
    float* cS = (float*)(sm + S_CS);
    float* part = (float*)(sm + S_PART);
    float* bS = (float*)(sm + S_BS);
    int tid = threadIdx.x, lane = tid & 31, wid = tid >> 5;
    int mb = blockIdx.x >> 5, nb = blockIdx.x & 31;
    int ng = wid & 3, kg = wid >> 2;
    unsigned* ctr = &g_cntA[mb * 32];

    {   // resident Wh slice [64][512] + Wi slice [64][256] + bias
        HF* Wh = (HF*)(sm + S_WH);
        HF* Wi = (HF*)(sm + S_WI);
        const HF* sh = g_Wh + (size_t)(nb * 64) * HS;
        const HF* si = g_Wi + (size_t)(nb * 64) * HIDD;
        for (int i = tid; i < 4096; i += 512) {
            int r = i >> 6, c8 = (i & 63) * 8;
            *(int4*)&Wh[r * WST_H + c8] = *(const int4*)&sh[(size_t)r * HS + c8];
        }
        for (int i = tid; i < 2048; i += 512) {
            int r = i >> 5, c8 = (i & 31) * 8;
            *(int4*)&Wi[r * WST_I + c8] = *(const int4*)&si[(size_t)r * HIDD + c8];
        }
        if (tid < 64) bS[tid] = g_bP[nb * 64 + tid];
    }
    for (int i = tid; i < 64 * 16; i += 512) cS[i] = 0.f;
    __syncthreads();

    int prow = tid >> 4, eu = tid & 15;    // epilogue rows prow, prow+32; unit eu
    const uint32_t hb = sb + S_HB;
    const uint32_t fb = sb + S_FB;

    float acc[4][2][4];
    // prologue: stage feats(0), compute its MMA contribution into acc
    {
        const HF* F = g_fH + (size_t)(mb * 64) * HIDD;
        stage_cp(fb, F, HIDD, tid);
        stage_cp(fb + CHUNK_BYTES, F + 128, HIDD, tid);
        CP_COMMIT();
        CP_WAIT0();
        __syncthreads();
#pragma unroll
        for (int a = 0; a < 4; a++)
#pragma unroll
            for (int b = 0; b < 2; b++)
#pragma unroll
                for (int e = 0; e < 4; e++) acc[a][b][e] = 0.f;
        mma_1p(fb, sb + S_WI, WST_I, kg, 0, ng, lane, acc);
        mma_1p(fb + CHUNK_BYTES, sb + S_WI, WST_I, kg, 8, ng, lane, acc);
    }

#pragma unroll 1
    for (int t = 0; t < T_STEPS; t++) {
        if (t > 0) {
            // wait for h(t-1) from this mb group, burst-stage, h MMA into acc
            if (tid == 0) flag_spin(ctr, (unsigned)t * 32u);
            __syncthreads();
            const HF* Ah = g_hH + ((size_t)(t - 1) * BATCH + mb * 64) * HS;
            stage_h_all(hb, Ah, tid);
            CP_COMMIT();
            CP_WAIT0();
            __syncthreads();
#pragma unroll
            for (int ch = 0; ch < 4; ch++)
                mma_1p(hb + ch * CHUNK_BYTES, sb + S_WH, WST_H, kg, ch * 8, ng, lane, acc);
        }
        __syncthreads();                    // MMAs done; h bufs dead -> part alias safe

        // single-round epilogue
        sts_part_all(part, acc, kg, ng, lane);
        __syncthreads();
#pragma unroll
        for (int r = 0; r < 2; r++) {
            int row = r * 32 + prow;
            float g0 = 0.f, g1 = 0.f, g2 = 0.f, g3 = 0.f;
#pragma unroll
            for (int k = 0; k < 4; k++) {
                float4 p = *(const float4*)&part[(k * 64 + row) * 68 + eu * 4];
                g0 += p.x; g1 += p.y; g2 += p.z; g3 += p.w;
            }
            float zi = g0 + bS[eu * 4 + 0];
            float zf = g1 + bS[eu * 4 + 1];
            float zg = g2 + bS[eu * 4 + 2];
            float zo = g3 + bS[eu * 4 + 3];
            int ci = row * 16 + eu;
            float cn = sigmf(zf) * cS[ci] + sigmf(zi) * tanhf(zg);
            cS[ci] = cn;
            float hv = sigmf(zo) * tanhf(cn);
            g_hH[((size_t)t * BATCH + mb * 64 + row) * HS + nb * 16 + eu] = __float2half(hv);
        }
        __syncthreads();                    // h stores done CTA-wide before arrive
        if (tid == 0) flag_arrive(ctr);

        // barrier-shadow work: stage feats(t+1) AND compute its MMA into acc
        if (t + 1 < T_STEPS) {
            const HF* F = g_fH + ((size_t)(t + 1) * BATCH + mb * 64) * HIDD;
            stage_cp(fb, F, HIDD, tid);
            stage_cp(fb + CHUNK_BYTES, F + 128, HIDD, tid);
            CP_COMMIT();
            CP_WAIT0();
            __syncthreads();
#pragma unroll
            for (int a = 0; a < 4; a++)
#pragma unroll
                for (int b = 0; b < 2; b++)
#pragma unroll
                    for (int e = 0; e < 4; e++) acc[a][b][e] = 0.f;
            mma_1p(fb, sb + S_WI, WST_I, kg, 0, ng, lane, acc);
            mma_1p(fb + CHUNK_BYTES, sb + S_WI, WST_I, kg, 8, ng, lane, acc);
        }
    }
}

// ---------------- heads: 4 rows per warp share every Wt LDS ----------------
__global__ void __launch_bounds__(256) heads_kernel(
    const float* __restrict__ Wmu, const float* __restrict__ bmu,
    const float* __restrict__ lstd, const float* __restrict__ Wv,
    const float* __restrict__ bv, float* __restrict__ out) {
    __shared__ float Wt[17 * HS];
    __shared__ float sig_s[16], bias_s[17];
    int tid = threadIdx.x;
    for (int i = tid; i < HS * ACTD; i += 256) {
        int k = i >> 4, a = i & 15;
        Wt[a * HS + k] = Wmu[(size_t)k * ACTD + a];
    }
    for (int i = tid; i < HS; i += 256) Wt[16 * HS + i] = Wv[i];
    if (tid < 16) { sig_s[tid] = expf(lstd[tid]); bias_s[tid] = bmu[tid]; }
    if (tid == 16) bias_s[16] = bv[0];
    __syncthreads();

    int warp = tid >> 5, lane = tid & 31;
    int step = gridDim.x * 32;
    for (int row = blockIdx.x * 32 + warp * 4; row < TBROWS; row += step) {
        const HF* h0 = g_hH + (size_t)row * HS;
        float a0[17], a1[17], a2[17], a3[17];
#pragma unroll
        for (int a = 0; a < 17; a++) { a0[a] = 0.f; a1[a] = 0.f; a2[a] = 0.f; a3[a] = 0.f; }
#pragma unroll 2
        for (int q = 0; q < 16; q++) {
            int idx = q * 32 + lane;
            float v0 = __half2float(h0[idx]);
            float v1 = __half2float(h0[HS + idx]);
            float v2 = __half2float(h0[2 * HS + idx]);
            float v3 = __half2float(h0[3 * HS + idx]);
#pragma unroll
            for (int a = 0; a < 17; a++) {
                float w = Wt[a * HS + idx];
                a0[a] += v0 * w; a1[a] += v1 * w; a2[a] += v2 * w; a3[a] += v3 * w;
            }
        }
#pragma unroll
        for (int a = 0; a < 17; a++)
#pragma unroll
            for (int off = 16; off > 0; off >>= 1) {
                a0[a] += __shfl_xor_sync(0xffffffffu, a0[a], off);
                a1[a] += __shfl_xor_sync(0xffffffffu, a1[a], off);
                a2[a] += __shfl_xor_sync(0xffffffffu, a2[a], off);
                a3[a] += __shfl_xor_sync(0xffffffffu, a3[a], off);
            }
        if (lane < 16) {
            out[(size_t)row * ACTD + lane] = a0[lane] + bias_s[lane];
            out[(size_t)(row + 1) * ACTD + lane] = a1[lane] + bias_s[lane];
            out[(size_t)(row + 2) * ACTD + lane] = a2[lane] + bias_s[lane];
            out[(size_t)(row + 3) * ACTD + lane] = a3[lane] + bias_s[lane];
            float sg = sig_s[lane];
            out[(size_t)TBROWS * ACTD + (size_t)row * ACTD + lane] = sg;
            out[(size_t)TBROWS * ACTD + (size_t)(row + 1) * ACTD + lane] = sg;
            out[(size_t)TBROWS * ACTD + (size_t)(row + 2) * ACTD + lane] = sg;
            out[(size_t)TBROWS * ACTD + (size_t)(row + 3) * ACTD + lane] = sg;
        }
        if (lane == 0) {
            out[(size_t)TBROWS * ACTD * 2 + row] = a0[16] + bias_s[16];
            out[(size_t)TBROWS * ACTD * 2 + row + 1] = a1[16] + bias_s[16];
            out[(size_t)TBROWS * ACTD * 2 + row + 2] = a2[16] + bias_s[16];
            out[(size_t)TBROWS * ACTD * 2 + row + 3] = a3[16] + bias_s[16];
        }
    }
}

// ---------------- launch ----------------
extern "C" void kernel_launch(void* const* d_in, const int* in_sizes, int n_in,
                              void* d_out, int out_size) {
    const float* x     = (const float*)d_in[0];
    const float* W_enc = (const float*)d_in[1];
    const float* b_enc = (const float*)d_in[2];
    const float* Wi    = (const float*)d_in[3];
    const float* Wh    = (const float*)d_in[4];
    const float* b_l   = (const float*)d_in[5];
    const float* W_mu  = (const float*)d_in[6];
    const float* b_mu  = (const float*)d_in[7];
    const float* lstd  = (const float*)d_in[8];
    const float* W_v   = (const float*)d_in[9];
    const float* b_v   = (const float*)d_in[10];
    float* out = (float*)d_out;

    cudaFuncSetAttribute(scan_mma_kernel, cudaFuncAttributeMaxDynamicSharedMemorySize, S_DYN);

    prep_kernel<<<1024, 256>>>(Wi, Wh, b_l);
    enc_kernel<<<dim3(HIDD / 64, TBROWS / 64), 256>>>(x, W_enc, b_enc);
    scan_mma_kernel<<<NCTA, 512, S_DYN>>>();
    heads_kernel<<<1024, 256>>>(W_mu, b_mu, lstd, W_v, b_v, out);
}

// round 16
// speedup vs baseline: 1.0356x; 1.0356x over previous
#include <cuda_runtime.h>
#include <cuda_fp16.h>
#include <math.h>
#include <stdint.h>

#define T_STEPS 256
#define BATCH   256
#define OBSD    128
#define HIDD    256
#define HS      512
#define G4      2048
#define ACTD    16
#define TBROWS  (T_STEPS * BATCH)
#define NCTA    128
typedef __half HF;

// ---------------- scratch (static device arrays; no cudaMalloc) ----------------
__device__ __align__(16) HF    g_fH[(size_t)TBROWS * HIDD];   // feats fp16
__device__ __align__(16) HF    g_hH[(size_t)TBROWS * HS];     // h fp16
__device__ __align__(16) HF    g_Wh[(size_t)G4 * HS];         // [n][k] permuted+transposed fp16
__device__ __align__(16) HF    g_Wi[(size_t)G4 * HIDD];
__device__ __align__(16) float g_bP[G4];
__device__ __align__(128) unsigned g_cntA[128];               // per-mb barrier counters (mb*32)

__device__ __forceinline__ float sigmf(float x) { return 1.0f / (1.0f + expf(-x)); }
__device__ __forceinline__ float geluf(float v) {
    float u = 0.7978845608028654f * (v + 0.044715f * v * v * v);
    return 0.5f * v * (1.0f + tanhf(u));
}
__device__ __forceinline__ uint32_t smem_u32(const void* p) {
    uint32_t a;
    asm("{ .reg .u64 t; cvta.to.shared.u64 t, %1; cvt.u32.u64 %0, t; }" : "=r"(a) : "l"(p));
    return a;
}
__device__ __forceinline__ void ldmx4(uint32_t addr, uint32_t* r) {
    asm volatile("ldmatrix.sync.aligned.m8n8.x4.shared.b16 {%0,%1,%2,%3}, [%4];"
        : "=r"(r[0]), "=r"(r[1]), "=r"(r[2]), "=r"(r[3]) : "r"(addr));
}
__device__ __forceinline__ void mma16816(float* d, const uint32_t* a, const uint32_t* b) {
    asm volatile("mma.sync.aligned.m16n8k16.row.col.f32.f16.f16.f32 "
        "{%0,%1,%2,%3}, {%4,%5,%6,%7}, {%8,%9}, {%0,%1,%2,%3};"
        : "+f"(d[0]), "+f"(d[1]), "+f"(d[2]), "+f"(d[3])
        : "r"(a[0]), "r"(a[1]), "r"(a[2]), "r"(a[3]), "r"(b[0]), "r"(b[1]));
}
#define CP_COMMIT() asm volatile("cp.async.commit_group;" ::: "memory")
#define CP_WAIT0()  asm volatile("cp.async.wait_group 0;" ::: "memory")
#define CP_WAIT1()  asm volatile("cp.async.wait_group 1;" ::: "memory")
#define CP_WAIT2()  asm volatile("cp.async.wait_group 2;" ::: "memory")
__device__ __forceinline__ void flag_arrive(unsigned* f) {
    asm volatile("red.release.gpu.global.add.u32 [%0], %1;" :: "l"(f), "r"(1u) : "memory");
}
__device__ __forceinline__ void flag_spin(const unsigned* f, unsigned target) {
    unsigned v;
    do {
        asm volatile("ld.acquire.gpu.global.u32 %0, [%1];" : "=r"(v) : "l"(f) : "memory");
    } while (v < target);
}

// A stage stride: 136 halves (272B, ≡16 mod 128 -> conflict-free ldmatrix)
#define AST 136
#define CHUNK_BYTES 17408          // 64 x 136 halves
// ---- scan SMEM map (bytes) ----
#define S_WH   0                   // Wh slice 64x520 halves = 66560
#define S_WI   66560               // Wi slice 64x264 halves = 33792
#define S_HB   100352              // h stage: 4 chunks x 17408 = 69632
#define S_PART 100352              // part[4][64][68] f32 = 69632 -> aliases all h bufs
#define S_FB   169984              // feats stage: 2 sub-chunks of 17408 = 34816
#define S_CS   204800              // cell state 64x16 fp32 = 4096
#define S_BS   208896              // bias slice 64 f32 = 256
#define S_DYN  209152
#define WST_H  520
#define WST_I  264

// cp.async one K=128 chunk (64 rows) of fp16 A into stage buffer (512 thr)
__device__ __forceinline__ void stage_cp(uint32_t dst, const HF* src, int ld, int tid) {
#pragma unroll
    for (int p = 0; p < 2; p++) {
        int j = tid + p * 512;
        int r = j >> 4, cb = j & 15;
        const HF* s = src + (size_t)r * ld + cb * 8;
        uint32_t d = dst + r * 272 + cb * 16;
        asm volatile("cp.async.cg.shared.global [%0], [%1], 16;" :: "r"(d), "l"(s));
    }
}

// Warp (ng in [0,4), kg in [0,4)): m64 x n16 tile, single fp16 pass,
// 2 ksteps (kg*2, kg*2+1) of a 128-col A chunk against W ksteps wkbase+...
__device__ __forceinline__ void mma_1p(uint32_t aBuf, uint32_t wBuf, int wst,
                                       int kg, int wkbase, int ng, int lane,
                                       float acc[4][2][4]) {
#pragma unroll
    for (int s = 0; s < 2; s++) {
        int lks = kg * 2 + s;
        int wks = wkbase + lks;
        uint32_t bh[4];
        int nrow = ng * 16 + (lane & 7) + ((lane >> 4) << 3);
        int kcol = wks * 16 + ((lane >> 3) & 1) * 8;
        ldmx4(wBuf + (nrow * wst + kcol) * 2, bh);
#pragma unroll
        for (int mt = 0; mt < 4; mt++) {
            uint32_t ah[4];
            int row = mt * 16 + (lane & 15);
            int col = lks * 16 + ((lane >> 4) << 3);
            ldmx4(aBuf + (row * AST + col) * 2, ah);
#pragma unroll
            for (int q = 0; q < 2; q++)
                mma16816(acc[mt][q], ah, &bh[q * 2]);
        }
    }
}

// STS all k-split partials: part[kg][64][68]
__device__ __forceinline__ void sts_part_all(float* part, float acc[4][2][4],
                                             int kg, int ng, int lane) {
#pragma unroll
    for (int mt = 0; mt < 4; mt++)
#pragma unroll
        for (int nt = 0; nt < 2; nt++) {
            int row0 = mt * 16 + (lane >> 2);
            int col = ng * 16 + nt * 8 + (lane & 3) * 2;
            *(float2*)&part[(kg * 64 + row0) * 68 + col] = *(float2*)&acc[mt][nt][0];
            *(float2*)&part[(kg * 64 + row0 + 8) * 68 + col] = *(float2*)&acc[mt][nt][2];
        }
}

// ---------------- prep: permuted+transposed fp16 weights ----------------
__global__ void prep_kernel(const float* __restrict__ Wi, const float* __restrict__ Wh,
                            const float* __restrict__ bl) {
    int stride = gridDim.x * blockDim.x;
    int idx = blockIdx.x * blockDim.x + threadIdx.x;
    for (int i = idx; i < G4 * HS; i += stride) {
        int n = i >> 9, k = i & (HS - 1);
        g_Wh[i] = __float2half(Wh[(size_t)k * G4 + (n & 3) * HS + (n >> 2)]);
    }
    for (int i = idx; i < G4 * HIDD; i += stride) {
        int n = i >> 8, k = i & (HIDD - 1);
        g_Wi[i] = __float2half(Wi[(size_t)k * G4 + (n & 3) * HS + (n >> 2)]);
    }
    for (int i = idx; i < G4; i += stride)
        g_bP[i] = bl[(i & 3) * HS + (i >> 2)];
    if (idx < 128) g_cntA[idx] = 0;
}

// ---------------- encoder: feats = gelu(x@W_enc + b) -> fp16 ----------------
__global__ void __launch_bounds__(256) enc_kernel(const float* __restrict__ A,
                                                  const float* __restrict__ B,
                                                  const float* __restrict__ bias) {
    __shared__ float As[64 * 68];
    __shared__ float Bs[64 * 64];
    int nb = blockIdx.x, mb = blockIdx.y, tid = threadIdx.x;
    int tn = tid & 15, tm = tid >> 4;
    float acc[4][4];
#pragma unroll
    for (int i = 0; i < 4; i++)
#pragma unroll
        for (int j = 0; j < 4; j++) acc[i][j] = 0.f;
    for (int kc = 0; kc < 2; kc++) {
        __syncthreads();
#pragma unroll
        for (int p = 0; p < 4; p++) {
            int idx = p * 256 + tid, r = idx >> 4, c4 = (idx & 15) << 2;
            *(float4*)&As[r * 68 + c4] = *(const float4*)&A[(size_t)(mb * 64 + r) * OBSD + kc * 64 + c4];
            *(float4*)&Bs[r * 64 + c4] = *(const float4*)&B[(size_t)(kc * 64 + r) * HIDD + nb * 64 + c4];
        }
        __syncthreads();
#pragma unroll 8
        for (int kk = 0; kk < 64; kk++) {
            float4 w = *(const float4*)&Bs[kk * 64 + tn * 4];
#pragma unroll
            for (int i = 0; i < 4; i++) {
                float a = As[(tm * 4 + i) * 68 + kk];
                acc[i][0] += a * w.x; acc[i][1] += a * w.y;
                acc[i][2] += a * w.z; acc[i][3] += a * w.w;
            }
        }
    }
    int n0 = nb * 64 + tn * 4;
    float4 bb = *(const float4*)&bias[n0];
#pragma unroll
    for (int i = 0; i < 4; i++) {
        int row = mb * 64 + tm * 4 + i;
        __align__(8) HF hb[4];
        hb[0] = __float2half(geluf(acc[i][0] + bb.x));
        hb[1] = __float2half(geluf(acc[i][1] + bb.y));
        hb[2] = __float2half(geluf(acc[i][2] + bb.z));
        hb[3] = __float2half(geluf(acc[i][3] + bb.w));
        *(int2*)(g_fH + (size_t)row * HIDD + n0) = *(int2*)hb;
    }
}

// ---------------- fused persistent LSTM scan (R13 overlap + split h waits) ----------------
// 128 CTAs = 4 mb(64 batch) x 32 nb(64 gate cols). 16 warps = 4 ng x 4 kg.
// Order per step: [barrier passed] -> issue h01, h23 bursts -> feats MMA (covers h01)
// -> h01 MMA (covers h23) -> h23 MMA -> epilogue -> arrive -> stage feats(t+1) in shadow.
__global__ void __launch_bounds__(512) scan_mma_kernel() {
    extern __shared__ char sm[];
    uint32_t sb = smem_u32(sm);
    float* cS = (float*)(sm + S_CS);
    float* part = (float*)(sm + S_PART);
    float* bS = (float*)(sm + S_BS);
    int tid = threadIdx.x, lane = tid & 31, wid = tid >> 5;
    int mb = blockIdx.x >> 5, nb = blockIdx.x & 31;
    int ng = wid & 3, kg = wid >> 2;
    unsigned* ctr = &g_cntA[mb * 32];

    {   // resident Wh slice [64][512] + Wi slice [64][256] + bias
        HF* Wh = (HF*)(sm + S_WH);
        HF* Wi = (HF*)(sm + S_WI);
        const HF* sh = g_Wh + (size_t)(nb * 64) * HS;
        const HF* si = g_Wi + (size_t)(nb * 64) * HIDD;
        for (int i = tid; i < 4096; i += 512) {
            int r = i >> 6, c8 = (i & 63) * 8;
            *(int4*)&Wh[r * WST_H + c8] = *(const int4*)&sh[(size_t)r * HS + c8];
        }
        for (int i = tid; i < 2048; i += 512) {
            int r = i >> 5, c8 = (i & 31) * 8;
            *(int4*)&Wi[r * WST_I + c8] = *(const int4*)&si[(size_t)r * HIDD + c8];
        }
        if (tid < 64) bS[tid] = g_bP[nb * 64 + tid];
    }
    for (int i = tid; i < 64 * 16; i += 512) cS[i] = 0.f;
    __syncthreads();

    int prow = tid >> 4, eu = tid & 15;    // epilogue rows prow, prow+32; unit eu
    const uint32_t hb = sb + S_HB;
    const uint32_t fb = sb + S_FB;

    // prologue: stage feats tile for t=0
    {
        const HF* F = g_fH + (size_t)(mb * 64) * HIDD;
        stage_cp(fb, F, HIDD, tid);
        stage_cp(fb + CHUNK_BYTES, F + 128, HIDD, tid);
        CP_COMMIT();
    }

#pragma unroll 1
    for (int t = 0; t < T_STEPS; t++) {
        float acc[4][2][4];
#pragma unroll
        for (int a = 0; a < 4; a++)
#pragma unroll
            for (int b = 0; b < 2; b++)
#pragma unroll
                for (int e = 0; e < 4; e++) acc[a][b][e] = 0.f;

        if (t > 0) {
            // issue both h half-bursts (separate groups); feats(t) group pends ahead
            const HF* Ah = g_hH + ((size_t)(t - 1) * BATCH + mb * 64) * HS;
            stage_cp(hb, Ah, HS, tid);
            stage_cp(hb + CHUNK_BYTES, Ah + 128, HS, tid);
            CP_COMMIT();                    // group: h01
            stage_cp(hb + 2 * CHUNK_BYTES, Ah + 256, HS, tid);
            stage_cp(hb + 3 * CHUNK_BYTES, Ah + 384, HS, tid);
            CP_COMMIT();                    // group: h23
            CP_WAIT2();                     // feats(t) resident
            __syncthreads();
        } else {
            CP_WAIT0();
            __syncthreads();
        }

        // feats @ Wi — overlaps h01/h23 arrival
        mma_1p(fb, sb + S_WI, WST_I, kg, 0, ng, lane, acc);
        mma_1p(fb + CHUNK_BYTES, sb + S_WI, WST_I, kg, 8, ng, lane, acc);

        if (t > 0) {
            CP_WAIT1();                     // h01 resident (h23 may pend)
            __syncthreads();
            mma_1p(hb, sb + S_WH, WST_H, kg, 0, ng, lane, acc);
            mma_1p(hb + CHUNK_BYTES, sb + S_WH, WST_H, kg, 8, ng, lane, acc);
            CP_WAIT0();                     // h23 resident
            __syncthreads();
            mma_1p(hb + 2 * CHUNK_BYTES, sb + S_WH, WST_H, kg, 16, ng, lane, acc);
            mma_1p(hb + 3 * CHUNK_BYTES, sb + S_WH, WST_H, kg, 24, ng, lane, acc);
        }
        __syncthreads();                    // MMAs done; h bufs dead -> part alias safe

        // single-round epilogue
        sts_part_all(part, acc, kg, ng, lane);
        __syncthreads();
#pragma unroll
        for (int r = 0; r < 2; r++) {
            int row = r * 32 + prow;
            float g0 = 0.f, g1 = 0.f, g2 = 0.f, g3 = 0.f;
#pragma unroll
            for (int k = 0; k < 4; k++) {
                float4 p = *(const float4*)&part[(k * 64 + row) * 68 + eu * 4];
                g0 += p.x; g1 += p.y; g2 += p.z; g3 += p.w;
            }
            float zi = g0 + bS[eu * 4 + 0];
            float zf = g1 + bS[eu * 4 + 1];
            float zg = g2 + bS[eu * 4 + 2];
            float zo = g3 + bS[eu * 4 + 3];
            int ci = row * 16 + eu;
            float cn = sigmf(zf) * cS[ci] + sigmf(zi) * tanhf(zg);
            cS[ci] = cn;
            float hv = sigmf(zo) * tanhf(cn);
            g_hH[((size_t)t * BATCH + mb * 64 + row) * HS + nb * 16 + eu] = __float2half(hv);
        }

        // release h(t); stage feats(t+1) during the spin
        __syncthreads();                    // h stores done CTA-wide before arrive
        if (tid == 0) flag_arrive(ctr);
        if (t + 1 < T_STEPS) {
            const HF* F = g_fH + ((size_t)(t + 1) * BATCH + mb * 64) * HIDD;
            stage_cp(fb, F, HIDD, tid);
            stage_cp(fb + CHUNK_BYTES, F + 128, HIDD, tid);
            CP_COMMIT();                    // group: feats(t+1)
        }
        if (tid == 0) flag_spin(ctr, (unsigned)(t + 1) * 32u);
        __syncthreads();                    // also fences part reads vs next h staging
    }
}

// ---------------- heads: 2 rows per warp share every Wt LDS (R13 best) ----------------
__global__ void __launch_bounds__(256) heads_kernel(
    const float* __restrict__ Wmu, const float* __restrict__ bmu,
    const float* __restrict__ lstd, const float* __restrict__ Wv,
    const float* __restrict__ bv, float* __restrict__ out) {
    __shared__ float Wt[17 * HS];
    __shared__ float sig_s[16], bias_s[17];
    int tid = threadIdx.x;
    for (int i = tid; i < HS * ACTD; i += 256) {
        int k = i >> 4, a = i & 15;
        Wt[a * HS + k] = Wmu[(size_t)k * ACTD + a];
    }
    for (int i = tid; i < HS; i += 256) Wt[16 * HS + i] = Wv[i];
    if (tid < 16) { sig_s[tid] = expf(lstd[tid]); bias_s[tid] = bmu[tid]; }
    if (tid == 16) bias_s[16] = bv[0];
    __syncthreads();

    int warp = tid >> 5, lane = tid & 31;
    int step = gridDim.x * 16;
    for (int row = blockIdx.x * 16 + warp * 2; row < TBROWS; row += step) {
        const HF* h0 = g_hH + (size_t)row * HS;
        const HF* h1 = h0 + HS;
        float a0[17], a1[17];
#pragma unroll
        for (int a = 0; a < 17; a++) { a0[a] = 0.f; a1[a] = 0.f; }
#pragma unroll 4
        for (int q = 0; q < 16; q++) {
            int idx = q * 32 + lane;
            float v0 = __half2float(h0[idx]);
            float v1 = __half2float(h1[idx]);
#pragma unroll
            for (int a = 0; a < 17; a++) {
                float w = Wt[a * HS + idx];
                a0[a] += v0 * w; a1[a] += v1 * w;
            }
        }
#pragma unroll
        for (int a = 0; a < 17; a++)
#pragma unroll
            for (int off = 16; off > 0; off >>= 1) {
                a0[a] += __shfl_xor_sync(0xffffffffu, a0[a], off);
                a1[a] += __shfl_xor_sync(0xffffffffu, a1[a], off);
            }
        if (lane < 16) {
            out[(size_t)row * ACTD + lane] = a0[lane] + bias_s[lane];
            out[(size_t)(row + 1) * ACTD + lane] = a1[lane] + bias_s[lane];
            out[(size_t)TBROWS * ACTD + (size_t)row * ACTD + lane] = sig_s[lane];
            out[(size_t)TBROWS * ACTD + (size_t)(row + 1) * ACTD + lane] = sig_s[lane];
        }
        if (lane == 0) {
            out[(size_t)TBROWS * ACTD * 2 + row] = a0[16] + bias_s[16];
            out[(size_t)TBROWS * ACTD * 2 + row + 1] = a1[16] + bias_s[16];
        }
    }
}

// ---------------- launch ----------------
extern "C" void kernel_launch(void* const* d_in, const int* in_sizes, int n_in,
                              void* d_out, int out_size) {
    const float* x     = (const float*)d_in[0];
    const float* W_enc = (const float*)d_in[1];
    const float* b_enc = (const float*)d_in[2];
    const float* Wi    = (const float*)d_in[3];
    const float* Wh    = (const float*)d_in[4];
    const float* b_l   = (const float*)d_in[5];
    const float* W_mu  = (const float*)d_in[6];
    const float* b_mu  = (const float*)d_in[7];
    const float* lstd  = (const float*)d_in[8];
    const float* W_v   = (const float*)d_in[9];
    const float* b_v   = (const float*)d_in[10];
    float* out = (float*)d_out;

    cudaFuncSetAttribute(scan_mma_kernel, cudaFuncAttributeMaxDynamicSharedMemorySize, S_DYN);

    prep_kernel<<<1024, 256>>>(Wi, Wh, b_l);
    enc_kernel<<<dim3(HIDD / 64, TBROWS / 64), 256>>>(x, W_enc, b_enc);
    scan_mma_kernel<<<NCTA, 512, S_DYN>>>();
    heads_kernel<<<1024, 256>>>(W_mu, b_mu, lstd, W_v, b_v, out);
}